// round 16
// baseline (speedup 1.0000x reference)
#include <cuda_runtime.h>
#include <cuda_bf16.h>
#include <math.h>
#include <stdint.h>

#define BB 64
#define SS 2048
#define EE 512
#define HH 512
#define TT 128
#define MTOT (BB * SS)

// ---------------------------------------------------------------------------
// Scratch (__device__ globals; no allocation allowed)
// ---------------------------------------------------------------------------
__device__ float g_ctxsum[BB * 16 * EE];
__device__ float g_count[BB * 16];
__device__ float g_u[BB * HH];
__device__ float g_mask[MTOT];
__device__ float g_spart[2 * MTOT];
__device__ float g_attn[BB * SS];
__device__ float g_rep[BB * 16 * EE];
__device__ __nv_bfloat16 g_Wh[HH * EE];   // [n][k] = W_att[k][n], hi part
__device__ __nv_bfloat16 g_Wl[HH * EE];   // lo part
__device__ __nv_bfloat16 g_Ah[(size_t)MTOT * EE];  // words hi  (128 MB)
__device__ __nv_bfloat16 g_Al[(size_t)MTOT * EE];  // words lo  (128 MB)

// ---------------------------------------------------------------------------
// PTX helpers
// ---------------------------------------------------------------------------
__device__ __forceinline__ uint32_t smem_to_u32(const void* p) {
    uint32_t a;
    asm("{ .reg .u64 t; cvta.to.shared.u64 t, %1; cvt.u32.u64 %0, t; }"
        : "=r"(a) : "l"(p));
    return a;
}

__device__ __forceinline__ void ldsm_x4(uint32_t* r, uint32_t addr) {
    asm volatile("ldmatrix.sync.aligned.m8n8.x4.shared.b16 {%0,%1,%2,%3}, [%4];"
                 : "=r"(r[0]), "=r"(r[1]), "=r"(r[2]), "=r"(r[3]) : "r"(addr));
}

__device__ __forceinline__ void mma16816(float* c, const uint32_t* a, const uint32_t* b) {
    asm volatile(
        "mma.sync.aligned.m16n8k16.row.col.f32.bf16.bf16.f32 "
        "{%0,%1,%2,%3}, {%4,%5,%6,%7}, {%8,%9}, {%0,%1,%2,%3};"
        : "+f"(c[0]), "+f"(c[1]), "+f"(c[2]), "+f"(c[3])
        : "r"(a[0]), "r"(a[1]), "r"(a[2]), "r"(a[3]), "r"(b[0]), "r"(b[1]));
}

__device__ __forceinline__ void cp16(uint32_t saddr, const void* g) {
    asm volatile("cp.async.cg.shared.global [%0], [%1], 16;" :: "r"(saddr), "l"(g));
}
#define CP_COMMIT() asm volatile("cp.async.commit_group;" ::: "memory")
template <int N>
__device__ __forceinline__ void cp_wait() {
    asm volatile("cp.async.wait_group %0;" :: "n"(N) : "memory");
}

// paired fast tanh: one RCP shared across two values (R15; neutral perf,
// slightly better rel_err). tanh(x) = 1 - 2/(e^{2x}+1).
__device__ __forceinline__ void tanh2_fast(float x0, float x1, float& t0, float& t1) {
    float e0 = __expf(2.f * fminf(x0, 20.f));
    float e1 = __expf(2.f * fminf(x1, 20.f));
    float d0 = e0 + 1.f, d1 = e1 + 1.f;
    float q = __fdividef(2.f, d0 * d1);
    t0 = 1.f - q * d1;
    t1 = 1.f - q * d0;
}

// ---------------------------------------------------------------------------
// Kernel A (fused prep): blocks [0,1024): colsums + counts + mask + bf16 hi/lo
// split of words (128 rows each). Blocks [1024,2048): W_att transpose+split.
// ---------------------------------------------------------------------------
__global__ void __launch_bounds__(256) ctx_prep_kernel(const float* __restrict__ words,
                                                       const float* __restrict__ Watt) {
    if (blockIdx.x >= 1024) {
        const int wblk = blockIdx.x - 1024;
        const int n = wblk >> 1;
        const int k = ((wblk & 1) << 8) + threadIdx.x;
        float w = Watt[(size_t)k * HH + n];
        __nv_bfloat16 hi = __float2bfloat16_rn(w);
        float r = w - __bfloat162float(hi);
        g_Wh[(size_t)n * EE + k] = hi;
        g_Wl[(size_t)n * EE + k] = __float2bfloat16_rn(r);
        return;
    }

    __shared__ float part[8][EE];
    __shared__ float cnt_sm[8];
    const int tid = threadIdx.x;
    const int warp = tid >> 5, lane = tid & 31;
    const int blk = blockIdx.x;
    const int b = blk >> 4, c = blk & 15;
    const int row0 = b * SS + c * 128;
    const float* wbase = words + (size_t)row0 * EE;

    float creg[16];
#pragma unroll
    for (int j = 0; j < 16; ++j) creg[j] = 0.f;
    float cnt = 0.f;

    for (int r = warp; r < 128; r += 8) {
        const float4* row = (const float4*)(wbase + (size_t)r * EE);
        const size_t grow = (size_t)(row0 + r);
        float rs = 0.f;
#pragma unroll
        for (int j = 0; j < 4; ++j) {
            float4 x = row[j * 32 + lane];
            rs += x.x + x.y + x.z + x.w;
            creg[j * 4 + 0] += x.x;
            creg[j * 4 + 1] += x.y;
            creg[j * 4 + 2] += x.z;
            creg[j * 4 + 3] += x.w;
            __nv_bfloat162 h01 = __float22bfloat162_rn(make_float2(x.x, x.y));
            __nv_bfloat162 h23 = __float22bfloat162_rn(make_float2(x.z, x.w));
            __nv_bfloat162 l01 = __float22bfloat162_rn(
                make_float2(x.x - __bfloat162float(h01.x), x.y - __bfloat162float(h01.y)));
            __nv_bfloat162 l23 = __float22bfloat162_rn(
                make_float2(x.z - __bfloat162float(h23.x), x.w - __bfloat162float(h23.y)));
            const size_t idx = grow * EE + (size_t)(j * 32 + lane) * 4;
            *(uint2*)&g_Ah[idx] = make_uint2(*(uint32_t*)&h01, *(uint32_t*)&h23);
            *(uint2*)&g_Al[idx] = make_uint2(*(uint32_t*)&l01, *(uint32_t*)&l23);
        }
#pragma unroll
        for (int o = 16; o > 0; o >>= 1) rs += __shfl_xor_sync(0xffffffffu, rs, o);
        if (lane == 0) {
            float valid = (rs != 0.f) ? 1.f : 0.f;
            g_mask[row0 + r] = valid;
            cnt += valid;
        }
    }
#pragma unroll
    for (int j = 0; j < 16; ++j) part[warp][(j >> 2) * 128 + lane * 4 + (j & 3)] = creg[j];
    if (lane == 0) cnt_sm[warp] = cnt;
    __syncthreads();

    for (int e = tid; e < EE; e += 256) {
        float s = 0.f;
#pragma unroll
        for (int w = 0; w < 8; ++w) s += part[w][e];
        g_ctxsum[blk * EE + e] = s;
    }
    if (tid == 0) {
        float s = 0.f;
#pragma unroll
        for (int w = 0; w < 8; ++w) s += cnt_sm[w];
        g_count[blk] = s;
    }
}

// ---------------------------------------------------------------------------
// Kernel B: u[b,h] = b_att[h] + (1/len) * sum_e ctxsum[b,e] * W_att[E+e, h]
// ---------------------------------------------------------------------------
__global__ void __launch_bounds__(512) u_kernel(const float* __restrict__ Watt,
                                                const float* __restrict__ b_att) {
    __shared__ float ctx[EE];
    __shared__ float leninv;
    const int b = blockIdx.x, tid = threadIdx.x;

    float s = 0.f;
#pragma unroll
    for (int c = 0; c < 16; ++c) s += g_ctxsum[(b * 16 + c) * EE + tid];
    ctx[tid] = s;
    if (tid == 0) {
        float len = 0.f;
#pragma unroll
        for (int c = 0; c < 16; ++c) len += g_count[b * 16 + c];
        leninv = 1.f / len;
    }
    __syncthreads();

    const float li = leninv;
    const float* Wb = Watt + (size_t)EE * HH;
    float acc = 0.f;
    for (int e = 0; e < EE; ++e) acc += ctx[e] * Wb[(size_t)e * HH + tid];
    g_u[b * HH + tid] = b_att[tid] + li * acc;
}

// ---------------------------------------------------------------------------
// Kernel C: tensor-core scores GEMM (R14 cp schedule; product order
// p0=Ah*Bh -> p2=Ah*Bl -> p1=Al*Bh so only 8 ldsm gate the first MMA of each
// k16; bl prefetched under p0 MMAs, al under p2 MMAs).
// CTA tile 128x256, 256 threads (8 warps, 64x64 each), BK=64, 2-stage.
// grid = 2048 (mtile*2 + ntile).
// ---------------------------------------------------------------------------
#define ST_AH 0
#define ST_AL 16384
#define ST_BH 32768
#define ST_BL 65536
#define ST_STRIDE 98304
#define SM_US 196608
#define SM_VS 197632
#define SM_RED 198656
#define SMEM_GEMM 200704

__global__ void __launch_bounds__(256, 1) scores_mma_kernel(const float* __restrict__ v) {
    extern __shared__ char smem[];
    const uint32_t sbase = smem_to_u32(smem);
    const int tid = threadIdx.x, wid = tid >> 5, lane = tid & 31;
    const int mt = blockIdx.x >> 1, nt = blockIdx.x & 1;
    const int m0 = mt * 128, n0 = nt * 256;
    const int b = m0 >> 11;

    float* u_s = (float*)(smem + SM_US);
    float* v_s = (float*)(smem + SM_VS);
    u_s[tid] = g_u[b * HH + n0 + tid];
    v_s[tid] = v[n0 + tid];

    // loader mapping: thread t -> (row = (t>>3) + 32*i, seg = t&7), 16B each
    const int lr = tid >> 3, lseg = tid & 7;
    const uint32_t soff = (uint32_t)(lr * 128 + ((lseg * 16) ^ ((lr & 7) << 4)));
    const __nv_bfloat16* pAh = g_Ah + (size_t)(m0 + lr) * EE + lseg * 8;
    const __nv_bfloat16* pAl = g_Al + (size_t)(m0 + lr) * EE + lseg * 8;
    const __nv_bfloat16* pBh = g_Wh + (size_t)(n0 + lr) * EE + lseg * 8;
    const __nv_bfloat16* pBl = g_Wl + (size_t)(n0 + lr) * EE + lseg * 8;

    // fragment addressing (SW128 swizzle); warp tile 64(m) x 64(n)
    const int matrix = lane >> 3, r8 = lane & 7;
    const int Wm = (wid >> 2) * 64, Wn = (wid & 3) * 64;
    const uint32_t akh = (uint32_t)((matrix >> 1) * 16);
    const uint32_t bkh = (uint32_t)((matrix & 1) * 16);
    uint32_t a_row_off[4], a_xor[4];
#pragma unroll
    for (int mf = 0; mf < 4; ++mf) {
        int arow = Wm + mf * 16 + r8 + (matrix & 1) * 8;
        a_row_off[mf] = (uint32_t)(arow * 128);
        a_xor[mf] = (uint32_t)((arow & 7) << 4);
    }
    uint32_t b_row_off[4], b_xor[4];
#pragma unroll
    for (int pr = 0; pr < 4; ++pr) {
        int nrow = Wn + pr * 16 + (matrix >> 1) * 8 + r8;
        b_row_off[pr] = (uint32_t)(nrow * 128);
        b_xor[pr] = (uint32_t)((nrow & 7) << 4);
    }

    float acc[4][8][4];
#pragma unroll
    for (int i = 0; i < 4; ++i)
#pragma unroll
        for (int j = 0; j < 8; ++j)
#pragma unroll
            for (int q = 0; q < 4; ++q) acc[i][j][q] = 0.f;

    // part 0: all A (8 cp16, DRAM latency -> earliest)
    // part 1: B i=0..3 (8 cp16); part 2: B i=4..7 (8 cp16) + commit
    auto issue_part = [&](int c, int buf, int p) {
        const uint32_t st = sbase + (uint32_t)buf * ST_STRIDE;
        const int kof = c * 64;
        if (p == 0) {
#pragma unroll
            for (int i = 0; i < 4; ++i) {
                cp16(st + ST_AH + soff + i * 4096, pAh + (size_t)i * 32 * EE + kof);
                cp16(st + ST_AL + soff + i * 4096, pAl + (size_t)i * 32 * EE + kof);
            }
        } else if (p < 3) {
            const int i0 = (p - 1) * 4;
#pragma unroll
            for (int j = 0; j < 4; ++j) {
                const int i = i0 + j;
                cp16(st + ST_BH + soff + i * 4096, pBh + (size_t)i * 32 * EE + kof);
                cp16(st + ST_BL + soff + i * 4096, pBl + (size_t)i * 32 * EE + kof);
            }
            if (p == 2) CP_COMMIT();
        }
    };

    // prologue: full chunk 0
    issue_part(0, 0, 0);
    issue_part(0, 0, 1);
    issue_part(0, 0, 2);

#pragma unroll 1
    for (int c = 0; c < 8; ++c) {
        cp_wait<0>();        // chunk c resident
        __syncthreads();     // publish chunk c; compute(c-1) done -> buf safe

        const uint32_t st = sbase + (uint32_t)(c & 1) * ST_STRIDE;
#pragma unroll
        for (int k16 = 0; k16 < 4; ++k16) {
            if (c < 7 && k16 < 3) issue_part(c + 1, (c + 1) & 1, k16);

            const uint32_t kA = (uint32_t)(k16 * 32) + akh;
            const uint32_t kB = (uint32_t)(k16 * 32) + bkh;
            uint32_t ah[4][4], bh[4][4], al[4][4], bl[4][4];
            // only ah + bh gate the first MMA (8 ldsm)
#pragma unroll
            for (int mf = 0; mf < 4; ++mf)
                ldsm_x4(ah[mf], st + ST_AH + a_row_off[mf] + (kA ^ a_xor[mf]));
#pragma unroll
            for (int pr = 0; pr < 4; ++pr)
                ldsm_x4(bh[pr], st + ST_BH + b_row_off[pr] + (kB ^ b_xor[pr]));
            // product 0: Ah x Bh
#pragma unroll
            for (int mf = 0; mf < 4; ++mf)
#pragma unroll
                for (int nf = 0; nf < 8; ++nf)
                    mma16816(acc[mf][nf], ah[mf], &bh[nf >> 1][(nf & 1) * 2]);
            // prefetch bl under p0 MMAs
#pragma unroll
            for (int pr = 0; pr < 4; ++pr)
                ldsm_x4(bl[pr], st + ST_BL + b_row_off[pr] + (kB ^ b_xor[pr]));
            // product 2: Ah x Bl (reuse ah)
#pragma unroll
            for (int mf = 0; mf < 4; ++mf)
#pragma unroll
                for (int nf = 0; nf < 8; ++nf)
                    mma16816(acc[mf][nf], ah[mf], &bl[nf >> 1][(nf & 1) * 2]);
            // prefetch al under p2 MMAs
#pragma unroll
            for (int mf = 0; mf < 4; ++mf)
                ldsm_x4(al[mf], st + ST_AL + a_row_off[mf] + (kA ^ a_xor[mf]));
            // product 1: Al x Bh (reuse bh)
#pragma unroll
            for (int mf = 0; mf < 4; ++mf)
#pragma unroll
                for (int nf = 0; nf < 8; ++nf)
                    mma16816(acc[mf][nf], al[mf], &bh[nf >> 1][(nf & 1) * 2]);
        }
    }
    __syncthreads();

    // epilogue: paired-RCP fast tanh + dot(v) over this CTA's 256 cols
    float* red = (float*)(smem + SM_RED);  // [128][4]
    const int g = lane >> 2, cq = (lane & 3) * 2;
#pragma unroll
    for (int mf = 0; mf < 4; ++mf) {
        float s0 = 0.f, s1 = 0.f;
#pragma unroll
        for (int nf = 0; nf < 8; ++nf) {
            const int col = Wn + nf * 8 + cq;
            const float u0 = u_s[col], u1 = u_s[col + 1];
            const float v0 = v_s[col], v1 = v_s[col + 1];
            float t0, t1;
            tanh2_fast(acc[mf][nf][0] + u0, acc[mf][nf][1] + u1, t0, t1);
            s0 += t0 * v0 + t1 * v1;
            tanh2_fast(acc[mf][nf][2] + u0, acc[mf][nf][3] + u1, t0, t1);
            s1 += t0 * v0 + t1 * v1;
        }
        s0 += __shfl_xor_sync(0xffffffffu, s0, 1);
        s0 += __shfl_xor_sync(0xffffffffu, s0, 2);
        s1 += __shfl_xor_sync(0xffffffffu, s1, 1);
        s1 += __shfl_xor_sync(0xffffffffu, s1, 2);
        if ((lane & 3) == 0) {
            red[(Wm + mf * 16 + g) * 4 + (wid & 3)] = s0;
            red[(Wm + mf * 16 + g + 8) * 4 + (wid & 3)] = s1;
        }
    }
    __syncthreads();

    if (tid < 128) {
        float sc = red[tid * 4] + red[tid * 4 + 1] + red[tid * 4 + 2] + red[tid * 4 + 3];
        g_spart[(size_t)nt * MTOT + m0 + tid] = sc;
    }
}

// ---------------------------------------------------------------------------
// Kernel D: masked softmax over S per batch (sums the 2 n-tile partials)
// ---------------------------------------------------------------------------
__global__ void __launch_bounds__(256) softmax_kernel() {
    __shared__ float redv[8];
    __shared__ float bval;
    const int b = blockIdx.x, tid = threadIdx.x;
    const int warp = tid >> 5, lane = tid & 31;

    float s[8];
    float mx = -3.4e38f;
#pragma unroll
    for (int i = 0; i < 8; ++i) {
        const int m = b * SS + tid + 256 * i;
        float sc = g_spart[m] + g_spart[MTOT + m];
        s[i] = (g_mask[m] != 0.f) ? sc : -1e30f;
        mx = fmaxf(mx, s[i]);
    }
#pragma unroll
    for (int o = 16; o > 0; o >>= 1) mx = fmaxf(mx, __shfl_xor_sync(0xffffffffu, mx, o));
    if (lane == 0) redv[warp] = mx;
    __syncthreads();
    if (tid == 0) {
        float m = redv[0];
#pragma unroll
        for (int w = 1; w < 8; ++w) m = fmaxf(m, redv[w]);
        bval = m;
    }
    __syncthreads();
    mx = bval;

    float sum = 0.f;
#pragma unroll
    for (int i = 0; i < 8; ++i) {
        s[i] = __expf(s[i] - mx);
        sum += s[i];
    }
#pragma unroll
    for (int o = 16; o > 0; o >>= 1) sum += __shfl_xor_sync(0xffffffffu, sum, o);
    __syncthreads();
    if (lane == 0) redv[warp] = sum;
    __syncthreads();
    if (tid == 0) {
        float t = 0.f;
#pragma unroll
        for (int w = 0; w < 8; ++w) t += redv[w];
        bval = 1.f / t;
    }
    __syncthreads();
    const float inv = bval;
#pragma unroll
    for (int i = 0; i < 8; ++i) g_attn[b * SS + tid + 256 * i] = s[i] * inv;
}

// ---------------------------------------------------------------------------
// Kernel E: partial rep (1024 blocks x 512 thr; 128 rows per block)
// ---------------------------------------------------------------------------
__global__ void __launch_bounds__(512) rep_kernel(const float* __restrict__ words) {
    __shared__ float a_sm[128];
    const int blk = blockIdx.x;
    const int b = blk >> 4, c = blk & 15;
    const int tid = threadIdx.x;
    if (tid < 128) a_sm[tid] = g_attn[b * SS + c * 128 + tid];
    __syncthreads();

    const float* wp = words + ((size_t)(b * SS + c * 128)) * EE + tid;
    float acc = 0.f;
#pragma unroll 8
    for (int i = 0; i < 128; ++i) acc += a_sm[i] * wp[(size_t)i * EE];
    g_rep[(size_t)blk * EE + tid] = acc;
}

// ---------------------------------------------------------------------------
// Kernel F: reduce rep partials + 3-layer MLP
// ---------------------------------------------------------------------------
__global__ void __launch_bounds__(512) mlp_kernel(const float* __restrict__ W1,
                                                  const float* __restrict__ b1,
                                                  const float* __restrict__ W2,
                                                  const float* __restrict__ b2,
                                                  const float* __restrict__ W3,
                                                  const float* __restrict__ b3,
                                                  float* __restrict__ out) {
    __shared__ float x[EE];
    __shared__ float h1[HH];
    __shared__ float h2[HH];
    const int b = blockIdx.x, tid = threadIdx.x;

    float r = 0.f;
#pragma unroll
    for (int c = 0; c < 16; ++c) r += g_rep[(size_t)(b * 16 + c) * EE + tid];
    x[tid] = r;
    __syncthreads();

    float a = b1[tid];
    for (int e = 0; e < EE; ++e) a += x[e] * W1[(size_t)e * HH + tid];
    h1[tid] = fmaxf(a, 0.f);
    __syncthreads();

    a = b2[tid];
    for (int e = 0; e < HH; ++e) a += h1[e] * W2[(size_t)e * HH + tid];
    h2[tid] = fmaxf(a, 0.f);
    __syncthreads();

    if (tid < TT) {
        a = b3[tid];
        for (int e = 0; e < HH; ++e) a += h2[e] * W3[(size_t)e * TT + tid];
        out[b * TT + tid] = a;
    }
}

// ---------------------------------------------------------------------------
extern "C" void kernel_launch(void* const* d_in, const int* in_sizes, int n_in,
                              void* d_out, int out_size) {
    const float* words = (const float*)d_in[0];
    const float* Watt  = (const float*)d_in[1];
    const float* b_att = (const float*)d_in[2];
    const float* v     = (const float*)d_in[3];
    const float* W1    = (const float*)d_in[4];
    const float* b1    = (const float*)d_in[5];
    const float* W2    = (const float*)d_in[6];
    const float* b2    = (const float*)d_in[7];
    const float* W3    = (const float*)d_in[8];
    const float* b3    = (const float*)d_in[9];
    float* out = (float*)d_out;

    cudaFuncSetAttribute(scores_mma_kernel, cudaFuncAttributeMaxDynamicSharedMemorySize,
                         SMEM_GEMM);

    ctx_prep_kernel<<<2048, 256>>>(words, Watt);
    u_kernel<<<BB, 512>>>(Watt, b_att);
    scores_mma_kernel<<<(MTOT / 128) * 2, 256, SMEM_GEMM>>>(v);
    softmax_kernel<<<BB, 256>>>();
    rep_kernel<<<BB * 16, 512>>>(words);
    mlp_kernel<<<BB, 512>>>(W1, b1, W2, b2, W3, b3, out);
}

// round 17
// speedup vs baseline: 1.0083x; 1.0083x over previous
#include <cuda_runtime.h>
#include <cuda_bf16.h>
#include <math.h>
#include <stdint.h>

#define BB 64
#define SS 2048
#define EE 512
#define HH 512
#define TT 128
#define MTOT (BB * SS)

// ---------------------------------------------------------------------------
// Scratch (__device__ globals; no allocation allowed)
// ---------------------------------------------------------------------------
__device__ float g_ctxsum[BB * 16 * EE];
__device__ float g_count[BB * 16];
__device__ float g_u[BB * HH];
__device__ float g_mask[MTOT];
__device__ float g_spart[2 * MTOT];
__device__ float g_attn[BB * SS];
__device__ float g_rep[BB * 16 * EE];
__device__ __nv_bfloat16 g_Wh[HH * EE];   // [n][k] = W_att[k][n], hi part
__device__ __nv_bfloat16 g_Wl[HH * EE];   // lo part
__device__ __nv_bfloat16 g_Ah[(size_t)MTOT * EE];  // words hi  (128 MB)
__device__ __nv_bfloat16 g_Al[(size_t)MTOT * EE];  // words lo  (128 MB)

// ---------------------------------------------------------------------------
// PTX helpers
// ---------------------------------------------------------------------------
__device__ __forceinline__ uint32_t smem_to_u32(const void* p) {
    uint32_t a;
    asm("{ .reg .u64 t; cvta.to.shared.u64 t, %1; cvt.u32.u64 %0, t; }"
        : "=r"(a) : "l"(p));
    return a;
}

__device__ __forceinline__ void ldsm_x4(uint32_t* r, uint32_t addr) {
    asm volatile("ldmatrix.sync.aligned.m8n8.x4.shared.b16 {%0,%1,%2,%3}, [%4];"
                 : "=r"(r[0]), "=r"(r[1]), "=r"(r[2]), "=r"(r[3]) : "r"(addr));
}

__device__ __forceinline__ void mma16816(float* c, const uint32_t* a, const uint32_t* b) {
    asm volatile(
        "mma.sync.aligned.m16n8k16.row.col.f32.bf16.bf16.f32 "
        "{%0,%1,%2,%3}, {%4,%5,%6,%7}, {%8,%9}, {%0,%1,%2,%3};"
        : "+f"(c[0]), "+f"(c[1]), "+f"(c[2]), "+f"(c[3])
        : "r"(a[0]), "r"(a[1]), "r"(a[2]), "r"(a[3]), "r"(b[0]), "r"(b[1]));
}

__device__ __forceinline__ void cp16(uint32_t saddr, const void* g) {
    asm volatile("cp.async.cg.shared.global [%0], [%1], 16;" :: "r"(saddr), "l"(g));
}
#define CP_COMMIT() asm volatile("cp.async.commit_group;" ::: "memory")
template <int N>
__device__ __forceinline__ void cp_wait() {
    asm volatile("cp.async.wait_group %0;" :: "n"(N) : "memory");
}

// fast tanh: 1 - 2/(e^{2x}+1); saturates correctly for |x| large (R14 version)
__device__ __forceinline__ float tanh_fast(float x) {
    float e = __expf(2.f * x);
    return 1.f - __fdividef(2.f, e + 1.f);
}

// ---------------------------------------------------------------------------
// Kernel A (fused prep): blocks [0,1024): colsums + counts + mask + bf16 hi/lo
// split of words (128 rows each). Blocks [1024,1280): W_att top-half
// transpose + split via coalesced smem 32x32 tile transpose.
// ---------------------------------------------------------------------------
__global__ void __launch_bounds__(256) ctx_prep_kernel(const float* __restrict__ words,
                                                       const float* __restrict__ Watt) {
    if (blockIdx.x >= 1024) {
        // --- wprep: 256 blocks, each a 32(k) x 32(n) tile of W_att top half
        __shared__ __nv_bfloat16 sh[32][33];
        __shared__ __nv_bfloat16 sl[32][33];
        const int wblk = blockIdx.x - 1024;
        const int k0 = (wblk >> 4) * 32, n0 = (wblk & 15) * 32;
        const int t = threadIdx.x;
        // load: 4 phases, coalesced over n (consecutive lanes -> consecutive n)
#pragma unroll
        for (int i = 0; i < 4; ++i) {
            const int kk = i * 8 + (t >> 5);
            const int nn = t & 31;
            float w = Watt[(size_t)(k0 + kk) * HH + n0 + nn];
            __nv_bfloat16 hi = __float2bfloat16_rn(w);
            sh[kk][nn] = hi;
            sl[kk][nn] = __float2bfloat16_rn(w - __bfloat162float(hi));
        }
        __syncthreads();
        // write: 4 phases, coalesced over k (consecutive lanes -> consecutive k)
#pragma unroll
        for (int i = 0; i < 4; ++i) {
            const int nn = i * 8 + (t >> 5);
            const int kk = t & 31;
            const size_t idx = (size_t)(n0 + nn) * EE + k0 + kk;
            g_Wh[idx] = sh[kk][nn];
            g_Wl[idx] = sl[kk][nn];
        }
        return;
    }

    __shared__ float part[8][EE];
    __shared__ float cnt_sm[8];
    const int tid = threadIdx.x;
    const int warp = tid >> 5, lane = tid & 31;
    const int blk = blockIdx.x;
    const int b = blk >> 4, c = blk & 15;
    const int row0 = b * SS + c * 128;
    const float* wbase = words + (size_t)row0 * EE;

    float creg[16];
#pragma unroll
    for (int j = 0; j < 16; ++j) creg[j] = 0.f;
    float cnt = 0.f;

    for (int r = warp; r < 128; r += 8) {
        const float4* row = (const float4*)(wbase + (size_t)r * EE);
        const size_t grow = (size_t)(row0 + r);
        float rs = 0.f;
#pragma unroll
        for (int j = 0; j < 4; ++j) {
            float4 x = row[j * 32 + lane];
            rs += x.x + x.y + x.z + x.w;
            creg[j * 4 + 0] += x.x;
            creg[j * 4 + 1] += x.y;
            creg[j * 4 + 2] += x.z;
            creg[j * 4 + 3] += x.w;
            __nv_bfloat162 h01 = __float22bfloat162_rn(make_float2(x.x, x.y));
            __nv_bfloat162 h23 = __float22bfloat162_rn(make_float2(x.z, x.w));
            __nv_bfloat162 l01 = __float22bfloat162_rn(
                make_float2(x.x - __bfloat162float(h01.x), x.y - __bfloat162float(h01.y)));
            __nv_bfloat162 l23 = __float22bfloat162_rn(
                make_float2(x.z - __bfloat162float(h23.x), x.w - __bfloat162float(h23.y)));
            const size_t idx = grow * EE + (size_t)(j * 32 + lane) * 4;
            *(uint2*)&g_Ah[idx] = make_uint2(*(uint32_t*)&h01, *(uint32_t*)&h23);
            *(uint2*)&g_Al[idx] = make_uint2(*(uint32_t*)&l01, *(uint32_t*)&l23);
        }
#pragma unroll
        for (int o = 16; o > 0; o >>= 1) rs += __shfl_xor_sync(0xffffffffu, rs, o);
        if (lane == 0) {
            float valid = (rs != 0.f) ? 1.f : 0.f;
            g_mask[row0 + r] = valid;
            cnt += valid;
        }
    }
#pragma unroll
    for (int j = 0; j < 16; ++j) part[warp][(j >> 2) * 128 + lane * 4 + (j & 3)] = creg[j];
    if (lane == 0) cnt_sm[warp] = cnt;
    __syncthreads();

    for (int e = tid; e < EE; e += 256) {
        float s = 0.f;
#pragma unroll
        for (int w = 0; w < 8; ++w) s += part[w][e];
        g_ctxsum[blk * EE + e] = s;
    }
    if (tid == 0) {
        float s = 0.f;
#pragma unroll
        for (int w = 0; w < 8; ++w) s += cnt_sm[w];
        g_count[blk] = s;
    }
}

// ---------------------------------------------------------------------------
// Kernel B: u[b,h] = b_att[h] + (1/len) * sum_e ctxsum[b,e] * W_att[E+e, h]
// ---------------------------------------------------------------------------
__global__ void __launch_bounds__(512) u_kernel(const float* __restrict__ Watt,
                                                const float* __restrict__ b_att) {
    __shared__ float ctx[EE];
    __shared__ float leninv;
    const int b = blockIdx.x, tid = threadIdx.x;

    float s = 0.f;
#pragma unroll
    for (int c = 0; c < 16; ++c) s += g_ctxsum[(b * 16 + c) * EE + tid];
    ctx[tid] = s;
    if (tid == 0) {
        float len = 0.f;
#pragma unroll
        for (int c = 0; c < 16; ++c) len += g_count[b * 16 + c];
        leninv = 1.f / len;
    }
    __syncthreads();

    const float li = leninv;
    const float* Wb = Watt + (size_t)EE * HH;
    float acc = 0.f;
    for (int e = 0; e < EE; ++e) acc += ctx[e] * Wb[(size_t)e * HH + tid];
    g_u[b * HH + tid] = b_att[tid] + li * acc;
}

// ---------------------------------------------------------------------------
// Kernel C: tensor-core scores GEMM — EXACT R14 champion configuration.
// cp spread: A(8)@k16=0, B[0..3](8)@k16=1, B[4..7](8)+commit@k16=2, k16=3
// cp-free. Product order p0=Ah*Bh -> p1=Al*Bh -> p2=Ah*Bl with al upfront,
// bl prefetched under p0 MMAs. CTA tile 128x256, 256 threads, BK=64, 2-stage.
// grid = 2048 (mtile*2 + ntile).
// ---------------------------------------------------------------------------
#define ST_AH 0
#define ST_AL 16384
#define ST_BH 32768
#define ST_BL 65536
#define ST_STRIDE 98304
#define SM_US 196608
#define SM_VS 197632
#define SM_RED 198656
#define SMEM_GEMM 200704

__global__ void __launch_bounds__(256, 1) scores_mma_kernel(const float* __restrict__ v) {
    extern __shared__ char smem[];
    const uint32_t sbase = smem_to_u32(smem);
    const int tid = threadIdx.x, wid = tid >> 5, lane = tid & 31;
    const int mt = blockIdx.x >> 1, nt = blockIdx.x & 1;
    const int m0 = mt * 128, n0 = nt * 256;
    const int b = m0 >> 11;

    float* u_s = (float*)(smem + SM_US);
    float* v_s = (float*)(smem + SM_VS);
    u_s[tid] = g_u[b * HH + n0 + tid];
    v_s[tid] = v[n0 + tid];

    // loader mapping: thread t -> (row = (t>>3) + 32*i, seg = t&7), 16B each
    const int lr = tid >> 3, lseg = tid & 7;
    const uint32_t soff = (uint32_t)(lr * 128 + ((lseg * 16) ^ ((lr & 7) << 4)));
    const __nv_bfloat16* pAh = g_Ah + (size_t)(m0 + lr) * EE + lseg * 8;
    const __nv_bfloat16* pAl = g_Al + (size_t)(m0 + lr) * EE + lseg * 8;
    const __nv_bfloat16* pBh = g_Wh + (size_t)(n0 + lr) * EE + lseg * 8;
    const __nv_bfloat16* pBl = g_Wl + (size_t)(n0 + lr) * EE + lseg * 8;

    // fragment addressing (SW128 swizzle); warp tile 64(m) x 64(n)
    const int matrix = lane >> 3, r8 = lane & 7;
    const int Wm = (wid >> 2) * 64, Wn = (wid & 3) * 64;
    const uint32_t akh = (uint32_t)((matrix >> 1) * 16);
    const uint32_t bkh = (uint32_t)((matrix & 1) * 16);
    uint32_t a_row_off[4], a_xor[4];
#pragma unroll
    for (int mf = 0; mf < 4; ++mf) {
        int arow = Wm + mf * 16 + r8 + (matrix & 1) * 8;
        a_row_off[mf] = (uint32_t)(arow * 128);
        a_xor[mf] = (uint32_t)((arow & 7) << 4);
    }
    uint32_t b_row_off[4], b_xor[4];
#pragma unroll
    for (int pr = 0; pr < 4; ++pr) {
        int nrow = Wn + pr * 16 + (matrix >> 1) * 8 + r8;
        b_row_off[pr] = (uint32_t)(nrow * 128);
        b_xor[pr] = (uint32_t)((nrow & 7) << 4);
    }

    float acc[4][8][4];
#pragma unroll
    for (int i = 0; i < 4; ++i)
#pragma unroll
        for (int j = 0; j < 8; ++j)
#pragma unroll
            for (int q = 0; q < 4; ++q) acc[i][j][q] = 0.f;

    // part 0: all A (8 cp16, DRAM latency -> earliest)
    // part 1: B i=0..3 (8 cp16); part 2: B i=4..7 (8 cp16) + commit
    auto issue_part = [&](int c, int buf, int p) {
        const uint32_t st = sbase + (uint32_t)buf * ST_STRIDE;
        const int kof = c * 64;
        if (p == 0) {
#pragma unroll
            for (int i = 0; i < 4; ++i) {
                cp16(st + ST_AH + soff + i * 4096, pAh + (size_t)i * 32 * EE + kof);
                cp16(st + ST_AL + soff + i * 4096, pAl + (size_t)i * 32 * EE + kof);
            }
        } else if (p < 3) {
            const int i0 = (p - 1) * 4;
#pragma unroll
            for (int j = 0; j < 4; ++j) {
                const int i = i0 + j;
                cp16(st + ST_BH + soff + i * 4096, pBh + (size_t)i * 32 * EE + kof);
                cp16(st + ST_BL + soff + i * 4096, pBl + (size_t)i * 32 * EE + kof);
            }
            if (p == 2) CP_COMMIT();
        }
    };

    // prologue: full chunk 0
    issue_part(0, 0, 0);
    issue_part(0, 0, 1);
    issue_part(0, 0, 2);

#pragma unroll 1
    for (int c = 0; c < 8; ++c) {
        cp_wait<0>();        // chunk c resident
        __syncthreads();     // publish chunk c; compute(c-1) done -> buf safe

        const uint32_t st = sbase + (uint32_t)(c & 1) * ST_STRIDE;
#pragma unroll
        for (int k16 = 0; k16 < 4; ++k16) {
            if (c < 7 && k16 < 3) issue_part(c + 1, (c + 1) & 1, k16);

            const uint32_t kA = (uint32_t)(k16 * 32) + akh;
            const uint32_t kB = (uint32_t)(k16 * 32) + bkh;
            uint32_t ah[4][4], bh[4][4], al[4][4], bl[4][4];
#pragma unroll
            for (int mf = 0; mf < 4; ++mf)
                ldsm_x4(ah[mf], st + ST_AH + a_row_off[mf] + (kA ^ a_xor[mf]));
#pragma unroll
            for (int pr = 0; pr < 4; ++pr)
                ldsm_x4(bh[pr], st + ST_BH + b_row_off[pr] + (kB ^ b_xor[pr]));
#pragma unroll
            for (int mf = 0; mf < 4; ++mf)
                ldsm_x4(al[mf], st + ST_AL + a_row_off[mf] + (kA ^ a_xor[mf]));
            // product 0: Ah x Bh
#pragma unroll
            for (int mf = 0; mf < 4; ++mf)
#pragma unroll
                for (int nf = 0; nf < 8; ++nf)
                    mma16816(acc[mf][nf], ah[mf], &bh[nf >> 1][(nf & 1) * 2]);
            // prefetch bl (covered by p1 MMAs)
#pragma unroll
            for (int pr = 0; pr < 4; ++pr)
                ldsm_x4(bl[pr], st + ST_BL + b_row_off[pr] + (kB ^ b_xor[pr]));
            // product 1: Al x Bh
#pragma unroll
            for (int mf = 0; mf < 4; ++mf)
#pragma unroll
                for (int nf = 0; nf < 8; ++nf)
                    mma16816(acc[mf][nf], al[mf], &bh[nf >> 1][(nf & 1) * 2]);
            // product 2: Ah x Bl
#pragma unroll
            for (int mf = 0; mf < 4; ++mf)
#pragma unroll
                for (int nf = 0; nf < 8; ++nf)
                    mma16816(acc[mf][nf], ah[mf], &bl[nf >> 1][(nf & 1) * 2]);
        }
    }
    __syncthreads();

    // epilogue: fast tanh + dot(v) over this CTA's 256 cols (R14 version)
    float* red = (float*)(smem + SM_RED);  // [128][4]
    const int g = lane >> 2, cq = (lane & 3) * 2;
#pragma unroll
    for (int mf = 0; mf < 4; ++mf) {
        float s0 = 0.f, s1 = 0.f;
#pragma unroll
        for (int nf = 0; nf < 8; ++nf) {
            const int col = Wn + nf * 8 + cq;
            const float u0 = u_s[col], u1 = u_s[col + 1];
            const float v0 = v_s[col], v1 = v_s[col + 1];
            s0 += tanh_fast(acc[mf][nf][0] + u0) * v0;
            s0 += tanh_fast(acc[mf][nf][1] + u1) * v1;
            s1 += tanh_fast(acc[mf][nf][2] + u0) * v0;
            s1 += tanh_fast(acc[mf][nf][3] + u1) * v1;
        }
        s0 += __shfl_xor_sync(0xffffffffu, s0, 1);
        s0 += __shfl_xor_sync(0xffffffffu, s0, 2);
        s1 += __shfl_xor_sync(0xffffffffu, s1, 1);
        s1 += __shfl_xor_sync(0xffffffffu, s1, 2);
        if ((lane & 3) == 0) {
            red[(Wm + mf * 16 + g) * 4 + (wid & 3)] = s0;
            red[(Wm + mf * 16 + g + 8) * 4 + (wid & 3)] = s1;
        }
    }
    __syncthreads();

    if (tid < 128) {
        float sc = red[tid * 4] + red[tid * 4 + 1] + red[tid * 4 + 2] + red[tid * 4 + 3];
        g_spart[(size_t)nt * MTOT + m0 + tid] = sc;
    }
}

// ---------------------------------------------------------------------------
// Kernel D: masked softmax over S per batch (sums the 2 n-tile partials)
// ---------------------------------------------------------------------------
__global__ void __launch_bounds__(256) softmax_kernel() {
    __shared__ float redv[8];
    __shared__ float bval;
    const int b = blockIdx.x, tid = threadIdx.x;
    const int warp = tid >> 5, lane = tid & 31;

    float s[8];
    float mx = -3.4e38f;
#pragma unroll
    for (int i = 0; i < 8; ++i) {
        const int m = b * SS + tid + 256 * i;
        float sc = g_spart[m] + g_spart[MTOT + m];
        s[i] = (g_mask[m] != 0.f) ? sc : -1e30f;
        mx = fmaxf(mx, s[i]);
    }
#pragma unroll
    for (int o = 16; o > 0; o >>= 1) mx = fmaxf(mx, __shfl_xor_sync(0xffffffffu, mx, o));
    if (lane == 0) redv[warp] = mx;
    __syncthreads();
    if (tid == 0) {
        float m = redv[0];
#pragma unroll
        for (int w = 1; w < 8; ++w) m = fmaxf(m, redv[w]);
        bval = m;
    }
    __syncthreads();
    mx = bval;

    float sum = 0.f;
#pragma unroll
    for (int i = 0; i < 8; ++i) {
        s[i] = __expf(s[i] - mx);
        sum += s[i];
    }
#pragma unroll
    for (int o = 16; o > 0; o >>= 1) sum += __shfl_xor_sync(0xffffffffu, sum, o);
    __syncthreads();
    if (lane == 0) redv[warp] = sum;
    __syncthreads();
    if (tid == 0) {
        float t = 0.f;
#pragma unroll
        for (int w = 0; w < 8; ++w) t += redv[w];
        bval = 1.f / t;
    }
    __syncthreads();
    const float inv = bval;
#pragma unroll
    for (int i = 0; i < 8; ++i) g_attn[b * SS + tid + 256 * i] = s[i] * inv;
}

// ---------------------------------------------------------------------------
// Kernel E: partial rep (1024 blocks x 512 thr; 128 rows per block)
// ---------------------------------------------------------------------------
__global__ void __launch_bounds__(512) rep_kernel(const float* __restrict__ words) {
    __shared__ float a_sm[128];
    const int blk = blockIdx.x;
    const int b = blk >> 4, c = blk & 15;
    const int tid = threadIdx.x;
    if (tid < 128) a_sm[tid] = g_attn[b * SS + c * 128 + tid];
    __syncthreads();

    const float* wp = words + ((size_t)(b * SS + c * 128)) * EE + tid;
    float acc = 0.f;
#pragma unroll 8
    for (int i = 0; i < 128; ++i) acc += a_sm[i] * wp[(size_t)i * EE];
    g_rep[(size_t)blk * EE + tid] = acc;
}

// ---------------------------------------------------------------------------
// Kernel F: reduce rep partials + 3-layer MLP
// ---------------------------------------------------------------------------
__global__ void __launch_bounds__(512) mlp_kernel(const float* __restrict__ W1,
                                                  const float* __restrict__ b1,
                                                  const float* __restrict__ W2,
                                                  const float* __restrict__ b2,
                                                  const float* __restrict__ W3,
                                                  const float* __restrict__ b3,
                                                  float* __restrict__ out) {
    __shared__ float x[EE];
    __shared__ float h1[HH];
    __shared__ float h2[HH];
    const int b = blockIdx.x, tid = threadIdx.x;

    float r = 0.f;
#pragma unroll
    for (int c = 0; c < 16; ++c) r += g_rep[(size_t)(b * 16 + c) * EE + tid];
    x[tid] = r;
    __syncthreads();

    float a = b1[tid];
    for (int e = 0; e < EE; ++e) a += x[e] * W1[(size_t)e * HH + tid];
    h1[tid] = fmaxf(a, 0.f);
    __syncthreads();

    a = b2[tid];
    for (int e = 0; e < HH; ++e) a += h1[e] * W2[(size_t)e * HH + tid];
    h2[tid] = fmaxf(a, 0.f);
    __syncthreads();

    if (tid < TT) {
        a = b3[tid];
        for (int e = 0; e < HH; ++e) a += h2[e] * W3[(size_t)e * TT + tid];
        out[b * TT + tid] = a;
    }
}

// ---------------------------------------------------------------------------
extern "C" void kernel_launch(void* const* d_in, const int* in_sizes, int n_in,
                              void* d_out, int out_size) {
    const float* words = (const float*)d_in[0];
    const float* Watt  = (const float*)d_in[1];
    const float* b_att = (const float*)d_in[2];
    const float* v     = (const float*)d_in[3];
    const float* W1    = (const float*)d_in[4];
    const float* b1    = (const float*)d_in[5];
    const float* W2    = (const float*)d_in[6];
    const float* b2    = (const float*)d_in[7];
    const float* W3    = (const float*)d_in[8];
    const float* b3    = (const float*)d_in[9];
    float* out = (float*)d_out;

    cudaFuncSetAttribute(scores_mma_kernel, cudaFuncAttributeMaxDynamicSharedMemorySize,
                         SMEM_GEMM);

    ctx_prep_kernel<<<1024 + 256, 256>>>(words, Watt);
    u_kernel<<<BB, 512>>>(Watt, b_att);
    scores_mma_kernel<<<(MTOT / 128) * 2, 256, SMEM_GEMM>>>(v);
    softmax_kernel<<<BB, 256>>>();
    rep_kernel<<<BB * 16, 512>>>(words);
    mlp_kernel<<<BB, 512>>>(W1, b1, W2, b2, W3, b3, out);
}